// round 1
// baseline (speedup 1.0000x reference)
#include <cuda_runtime.h>
#include <cuda_bf16.h>

// Problem constants (fixed shapes from reference: B=64, C=1, H=W=512)
#define BATCH        64
#define NPER         262144           // C*H*W elements per sample
#define BLK_PER_S    16               // blocks per sample (pass 1)
#define THREADS1     256
#define ELEMS_PER_T  (NPER / (BLK_PER_S * THREADS1))   // 64 elements
#define VEC_PER_T    (ELEMS_PER_T / 4)                 // 16 float4s

struct St {
    float m;      // running max of t
    int   E;      // #{t == m}
    int   A;      // #{t == m && p > 0.5}
    int   S;      // #{p > 0.5}
    float sp;     // sum p
    float st;     // sum t
    float spt;    // sum p*t
};

__device__ St g_partials[BATCH * BLK_PER_S];

__device__ __forceinline__ void st_combine(St& a, const St& b) {
    if (b.m > a.m) { a.m = b.m; a.E = b.E; a.A = b.A; }
    else if (b.m == a.m) { a.E += b.E; a.A += b.A; }
    a.S  += b.S;
    a.sp += b.sp;
    a.st += b.st;
    a.spt += b.spt;
}

__device__ __forceinline__ St st_shfl_down(const St& a, int off, int width) {
    St o;
    o.m   = __shfl_down_sync(0xFFFFFFFFu, a.m,   off, width);
    o.E   = __shfl_down_sync(0xFFFFFFFFu, a.E,   off, width);
    o.A   = __shfl_down_sync(0xFFFFFFFFu, a.A,   off, width);
    o.S   = __shfl_down_sync(0xFFFFFFFFu, a.S,   off, width);
    o.sp  = __shfl_down_sync(0xFFFFFFFFu, a.sp,  off, width);
    o.st  = __shfl_down_sync(0xFFFFFFFFu, a.st,  off, width);
    o.spt = __shfl_down_sync(0xFFFFFFFFu, a.spt, off, width);
    return o;
}

__global__ __launch_bounds__(THREADS1)
void dice_pass1(const float* __restrict__ probs, const float* __restrict__ targs) {
    const int b      = blockIdx.x / BLK_PER_S;      // sample
    const int blkIn  = blockIdx.x % BLK_PER_S;
    const int tid    = threadIdx.x;

    // float4 base index for this block within the flat [B*N] array
    const int base4 = b * (NPER / 4) + blkIn * (NPER / (BLK_PER_S * 4));
    const float4* __restrict__ p4 = reinterpret_cast<const float4*>(probs) + base4;
    const float4* __restrict__ t4 = reinterpret_cast<const float4*>(targs) + base4;

    St s;
    s.m = -3.402823466e38f; s.E = 0; s.A = 0; s.S = 0;
    s.sp = 0.f; s.st = 0.f; s.spt = 0.f;

    #pragma unroll
    for (int k = 0; k < VEC_PER_T; k++) {
        const float4 pv = p4[tid + k * THREADS1];
        const float4 tv = t4[tid + k * THREADS1];

        #pragma unroll
        for (int j = 0; j < 4; j++) {
            const float p = (&pv.x)[j];
            const float t = (&tv.x)[j];
            const int sr = (p > 0.5f) ? 1 : 0;
            if (t > s.m)       { s.m = t; s.E = 1;  s.A = sr; }
            else if (t == s.m) { s.E++;             s.A += sr; }
            s.S   += sr;
            s.sp  += p;
            s.st  += t;
            s.spt += p * t;
        }
    }

    // warp reduce (width 32)
    #pragma unroll
    for (int off = 16; off > 0; off >>= 1) {
        St o = st_shfl_down(s, off, 32);
        st_combine(s, o);
    }

    __shared__ St warpRes[THREADS1 / 32];
    const int wid = tid >> 5, lid = tid & 31;
    if (lid == 0) warpRes[wid] = s;
    __syncthreads();

    if (wid == 0) {
        if (lid < (THREADS1 / 32)) s = warpRes[lid];
        #pragma unroll
        for (int off = (THREADS1 / 64); off > 0; off >>= 1) {
            St o = st_shfl_down(s, off, THREADS1 / 32);
            if (lid + off < (THREADS1 / 32)) st_combine(s, o);
        }
        if (lid == 0) g_partials[b * BLK_PER_S + blkIn] = s;
    }
}

__global__ __launch_bounds__(1024)
void dice_pass2(float* __restrict__ out) {
    const int tid  = threadIdx.x;
    const int g    = tid >> 4;       // sample 0..63
    const int lane = tid & 15;

    St s = g_partials[g * BLK_PER_S + lane];

    // fold 16 partials per sample (subgroups of 16 within a warp)
    #pragma unroll
    for (int off = 8; off > 0; off >>= 1) {
        St o = st_shfl_down(s, off, 16);
        st_combine(s, o);
    }

    __shared__ float terms[BATCH];
    if (lane == 0) {
        const int corr = NPER - s.E - s.S + 2 * s.A;
        // acc = corr / C with C = 1
        const float dice = 2.0f * (s.spt + 1.0f) / (s.sp + s.st + 1.0f);
        const float score = (corr == 1) ? 1.0f : dice;
        terms[g] = 1.0f - score;
    }
    __syncthreads();

    if (tid == 0) {
        float acc = 0.f;
        #pragma unroll
        for (int i = 0; i < BATCH; i++) acc += terms[i];
        out[0] = acc / (float)BATCH;
    }
}

extern "C" void kernel_launch(void* const* d_in, const int* in_sizes, int n_in,
                              void* d_out, int out_size) {
    const float* probs = (const float*)d_in[0];
    const float* targs = (const float*)d_in[1];
    float* out = (float*)d_out;

    dice_pass1<<<BATCH * BLK_PER_S, THREADS1>>>(probs, targs);
    dice_pass2<<<1, 1024>>>(out);
}